// round 1
// baseline (speedup 1.0000x reference)
#include <cuda_runtime.h>

#define BT 32768
#define NF 32
#define NU 64
#define EPS 1e-3f

// ---- output layout: out [BT,64] at offset 0, w [BT,32] at offset BT*64 ----
#define OUT_ELEMS (BT * NU)
#define W_OFF     OUT_ELEMS

__device__ __forceinline__ float eluf(float z)  { return z > 0.f ? z : (expf(z) - 1.f); }
__device__ __forceinline__ float sigmf(float z) { return 1.f / (1.f + expf(-z)); }

// ============================================================================
// Kernel 1: variable-weights GRN over F=32 + LayerNorm + softmax -> w [BT, 32]
// One thread per token; 4 matvecs 32x32 from smem (uniform broadcast reads).
// ============================================================================
__global__ __launch_bounds__(128) void k_weights(
    const float* __restrict__ x,
    const float* __restrict__ w1w, const float* __restrict__ b1w,
    const float* __restrict__ w2w, const float* __restrict__ b2w,
    const float* __restrict__ wg1w, const float* __restrict__ bg1w,
    const float* __restrict__ wg2w, const float* __restrict__ bg2w,
    const float* __restrict__ gammaw, const float* __restrict__ betaw,
    float* __restrict__ wout)
{
    __shared__ float s1[1024], s2[1024], sg1[1024], sg2[1024];
    __shared__ float vb1[32], vb2[32], vbg1[32], vbg2[32], vg[32], vbt[32];
    __shared__ float xsh[128 * 33];   // padded rows: bank-conflict-free column reads

    const int tid = threadIdx.x;
    for (int i = tid; i < 1024; i += 128) {
        s1[i] = w1w[i]; s2[i] = w2w[i]; sg1[i] = wg1w[i]; sg2[i] = wg2w[i];
    }
    if (tid < 32) {
        vb1[tid] = b1w[tid];  vb2[tid] = b2w[tid];
        vbg1[tid] = bg1w[tid]; vbg2[tid] = bg2w[tid];
        vg[tid] = gammaw[tid]; vbt[tid] = betaw[tid];
    }
    const int token = blockIdx.x * 128 + tid;
    {
        const float4* xp = (const float4*)(x + (size_t)token * NF);
        #pragma unroll
        for (int i = 0; i < 8; i++) {
            float4 v = xp[i];
            xsh[tid * 33 + i * 4 + 0] = v.x;
            xsh[tid * 33 + i * 4 + 1] = v.y;
            xsh[tid * 33 + i * 4 + 2] = v.z;
            xsh[tid * 33 + i * 4 + 3] = v.w;
        }
    }
    __syncthreads();

    float h[32];
    #pragma unroll
    for (int g = 0; g < 32; g++) h[g] = vb1[g];
    for (int f = 0; f < 32; f++) {
        float xv = xsh[tid * 33 + f];
        #pragma unroll
        for (int g = 0; g < 32; g++) h[g] += xv * s1[f * 32 + g];
    }
    #pragma unroll
    for (int g = 0; g < 32; g++) h[g] = eluf(h[g]);

    float h2[32];
    #pragma unroll
    for (int g = 0; g < 32; g++) h2[g] = vb2[g];
    for (int f = 0; f < 32; f++) {
        float hv = h[f];
        #pragma unroll
        for (int g = 0; g < 32; g++) h2[g] += hv * s2[f * 32 + g];
    }

    float o2[32];
    #pragma unroll
    for (int g = 0; g < 32; g++) o2[g] = vbg2[g];
    for (int f = 0; f < 32; f++) {
        float hv = h2[f];
        #pragma unroll
        for (int g = 0; g < 32; g++) o2[g] += hv * sg2[f * 32 + g];
    }
    #pragma unroll
    for (int g = 0; g < 32; g++) o2[g] = sigmf(o2[g]);

    // o1 into h (reuse)
    #pragma unroll
    for (int g = 0; g < 32; g++) h[g] = vbg1[g];
    for (int f = 0; f < 32; f++) {
        float hv = h2[f];
        #pragma unroll
        for (int g = 0; g < 32; g++) h[g] += hv * sg1[f * 32 + g];
    }
    // s = glu + residual
    #pragma unroll
    for (int g = 0; g < 32; g++) h[g] = h[g] * o2[g] + xsh[tid * 33 + g];

    // LayerNorm (biased var, eps=1e-3)
    float sum = 0.f, sq = 0.f;
    #pragma unroll
    for (int g = 0; g < 32; g++) { sum += h[g]; sq += h[g] * h[g]; }
    float mean = sum * (1.f / 32.f);
    float var  = sq * (1.f / 32.f) - mean * mean;
    float inv  = rsqrtf(var + EPS);

    float mx = -1e30f;
    #pragma unroll
    for (int g = 0; g < 32; g++) {
        float y = (h[g] - mean) * inv * vg[g] + vbt[g];
        h[g] = y;
        mx = fmaxf(mx, y);
    }
    float se = 0.f;
    #pragma unroll
    for (int g = 0; g < 32; g++) { float e = expf(h[g] - mx); h[g] = e; se += e; }
    float r = 1.f / se;
    #pragma unroll
    for (int g = 0; g < 32; g++) wout[(size_t)token * NF + g] = h[g] * r;
}

// ============================================================================
// Kernel 2: per-feature GRNs + LN + softmax-weighted sum over features.
// Block = 128 tokens, 512 threads. Thread = (4 tokens) x (4 U-columns).
// Loops features, stages [64x64] W2/Wg1/Wg2 in smem, accumulates in registers.
// ============================================================================
#define K2_THREADS 512
#define K2_TOK     128

// smem layout (floats)
#define SM_WB   0                    // 3 * 4096
#define SM_H1   12288                // 128 * 65 (padded)
#define SM_H2   (SM_H1 + 128 * 65)
#define SM_XS   (SM_H2 + 128 * 65)   // 128 * 32
#define SM_WS   (SM_XS + 128 * 32)   // 128 * 32
#define SM_VEC  (SM_WS + 128 * 32)   // 9 * 64
#define SM_FLOATS (SM_VEC + 9 * 64)

__global__ __launch_bounds__(K2_THREADS) void k_vsn(
    const float* __restrict__ x,
    const float* __restrict__ W1,  const float* __restrict__ b1,
    const float* __restrict__ W2,  const float* __restrict__ b2,
    const float* __restrict__ Wg1, const float* __restrict__ bg1,
    const float* __restrict__ Wg2, const float* __restrict__ bg2,
    const float* __restrict__ Wp,  const float* __restrict__ bp,
    const float* __restrict__ gamma, const float* __restrict__ beta,
    const float* __restrict__ w,
    float* __restrict__ out)
{
    extern __shared__ float sm[];
    float* Wb  = sm + SM_WB;
    float* h1s = sm + SM_H1;
    float* h2s = sm + SM_H2;
    float* xs  = sm + SM_XS;
    float* ws  = sm + SM_WS;
    float* w1v  = sm + SM_VEC;
    float* b1v  = w1v + 64;
    float* b2v  = b1v + 64;
    float* bg1v = b2v + 64;
    float* bg2v = bg1v + 64;
    float* wpv  = bg2v + 64;
    float* bpv  = wpv + 64;
    float* gv   = bpv + 64;
    float* bv   = gv + 64;

    const int tid  = threadIdx.x;
    const int set  = tid >> 4;    // 0..31 -> 4-token group
    const int vq   = tid & 15;    // 0..15 -> 4 U-columns
    const int v0   = vq * 4;
    const int tokb = set * 4;
    const size_t blk = (size_t)blockIdx.x * K2_TOK;

    // stage x / w tiles (each 128x32 f32, contiguous)
    {
        const float4* xg = (const float4*)(x + blk * NF);
        const float4* wg = (const float4*)(w + blk * NF);
        float4* xs4 = (float4*)xs;
        float4* ws4 = (float4*)ws;
        for (int i = tid; i < K2_TOK * NF / 4; i += K2_THREADS) {
            xs4[i] = xg[i];
            ws4[i] = wg[i];
        }
    }

    float acc[4][4];
    #pragma unroll
    for (int k = 0; k < 4; k++)
        #pragma unroll
        for (int j = 0; j < 4; j++) acc[k][j] = 0.f;

    for (int f = 0; f < NF; f++) {
        __syncthreads();   // previous iteration done with smem (and first: tiles staged)
        // stage per-feature weights
        {
            const float4* a = (const float4*)(W2  + (size_t)f * 4096);
            const float4* bm = (const float4*)(Wg1 + (size_t)f * 4096);
            const float4* c = (const float4*)(Wg2 + (size_t)f * 4096);
            float4* Wb4 = (float4*)Wb;
            for (int i = tid; i < 1024; i += K2_THREADS) {
                Wb4[i]        = a[i];
                Wb4[1024 + i] = bm[i];
                Wb4[2048 + i] = c[i];
            }
            if (tid < 64) {
                int o = f * 64 + tid;
                w1v[tid] = W1[o];  b1v[tid] = b1[o];  b2v[tid] = b2[o];
                bg1v[tid] = bg1[o]; bg2v[tid] = bg2[o];
                wpv[tid] = Wp[o];  bpv[tid] = bp[o];
                gv[tid] = gamma[o]; bv[tid] = beta[o];
            }
        }
        __syncthreads();

        // h1 = elu(x * W1_row + b1_row) : each thread fills its 4x4 slots
        #pragma unroll
        for (int k = 0; k < 4; k++) {
            float xv = xs[(tokb + k) * NF + f];
            #pragma unroll
            for (int j = 0; j < 4; j++) {
                int v = v0 + j;
                h1s[(tokb + k) * 65 + v] = eluf(xv * w1v[v] + b1v[v]);
            }
        }
        __syncthreads();

        // h2 = h1 @ W2 + b2
        float a2[4][4];
        #pragma unroll
        for (int k = 0; k < 4; k++)
            #pragma unroll
            for (int j = 0; j < 4; j++) a2[k][j] = b2v[v0 + j];
        #pragma unroll 4
        for (int u = 0; u < NU; u++) {
            float4 wv = *(const float4*)&Wb[u * 64 + v0];
            float ha = h1s[(tokb + 0) * 65 + u];
            float hb = h1s[(tokb + 1) * 65 + u];
            float hc = h1s[(tokb + 2) * 65 + u];
            float hd = h1s[(tokb + 3) * 65 + u];
            a2[0][0] += ha * wv.x; a2[0][1] += ha * wv.y; a2[0][2] += ha * wv.z; a2[0][3] += ha * wv.w;
            a2[1][0] += hb * wv.x; a2[1][1] += hb * wv.y; a2[1][2] += hb * wv.z; a2[1][3] += hb * wv.w;
            a2[2][0] += hc * wv.x; a2[2][1] += hc * wv.y; a2[2][2] += hc * wv.z; a2[2][3] += hc * wv.w;
            a2[3][0] += hd * wv.x; a2[3][1] += hd * wv.y; a2[3][2] += hd * wv.z; a2[3][3] += hd * wv.w;
        }
        #pragma unroll
        for (int k = 0; k < 4; k++)
            #pragma unroll
            for (int j = 0; j < 4; j++) h2s[(tokb + k) * 65 + v0 + j] = a2[k][j];
        __syncthreads();

        // o1 = h2@Wg1 + bg1 ; o2 = h2@Wg2 + bg2 (shared h2 reads)
        float o1[4][4], o2g[4][4];
        #pragma unroll
        for (int k = 0; k < 4; k++)
            #pragma unroll
            for (int j = 0; j < 4; j++) { o1[k][j] = bg1v[v0 + j]; o2g[k][j] = bg2v[v0 + j]; }
        #pragma unroll 4
        for (int u = 0; u < NU; u++) {
            float4 wa = *(const float4*)&Wb[4096 + u * 64 + v0];
            float4 wb = *(const float4*)&Wb[8192 + u * 64 + v0];
            float ha = h2s[(tokb + 0) * 65 + u];
            float hb = h2s[(tokb + 1) * 65 + u];
            float hc = h2s[(tokb + 2) * 65 + u];
            float hd = h2s[(tokb + 3) * 65 + u];
            o1[0][0] += ha * wa.x; o1[0][1] += ha * wa.y; o1[0][2] += ha * wa.z; o1[0][3] += ha * wa.w;
            o1[1][0] += hb * wa.x; o1[1][1] += hb * wa.y; o1[1][2] += hb * wa.z; o1[1][3] += hb * wa.w;
            o1[2][0] += hc * wa.x; o1[2][1] += hc * wa.y; o1[2][2] += hc * wa.z; o1[2][3] += hc * wa.w;
            o1[3][0] += hd * wa.x; o1[3][1] += hd * wa.y; o1[3][2] += hd * wa.z; o1[3][3] += hd * wa.w;
            o2g[0][0] += ha * wb.x; o2g[0][1] += ha * wb.y; o2g[0][2] += ha * wb.z; o2g[0][3] += ha * wb.w;
            o2g[1][0] += hb * wb.x; o2g[1][1] += hb * wb.y; o2g[1][2] += hb * wb.z; o2g[1][3] += hb * wb.w;
            o2g[2][0] += hc * wb.x; o2g[2][1] += hc * wb.y; o2g[2][2] += hc * wb.z; o2g[2][3] += hc * wb.w;
            o2g[3][0] += hd * wb.x; o2g[3][1] += hd * wb.y; o2g[3][2] += hd * wb.z; o2g[3][3] += hd * wb.w;
        }

        // s = glu + residual ; per-token LN over 64 (16 lanes x 4 vals) ; weighted acc
        float sum[4], sq[4];
        #pragma unroll
        for (int k = 0; k < 4; k++) {
            float xv = xs[(tokb + k) * NF + f];
            float su = 0.f, sv2 = 0.f;
            #pragma unroll
            for (int j = 0; j < 4; j++) {
                int v = v0 + j;
                float res = xv * wpv[v] + bpv[v];
                float sv = o1[k][j] * sigmf(o2g[k][j]) + res;
                o1[k][j] = sv;
                su += sv; sv2 += sv * sv;
            }
            sum[k] = su; sq[k] = sv2;
        }
        #pragma unroll
        for (int off = 1; off < 16; off <<= 1) {
            #pragma unroll
            for (int k = 0; k < 4; k++) {
                sum[k] += __shfl_xor_sync(0xffffffffu, sum[k], off);
                sq[k]  += __shfl_xor_sync(0xffffffffu, sq[k],  off);
            }
        }
        #pragma unroll
        for (int k = 0; k < 4; k++) {
            float mean = sum[k] * (1.f / 64.f);
            float var  = sq[k] * (1.f / 64.f) - mean * mean;
            float inv  = rsqrtf(var + EPS);
            float wf   = ws[(tokb + k) * NF + f];
            #pragma unroll
            for (int j = 0; j < 4; j++) {
                int v = v0 + j;
                float y = (o1[k][j] - mean) * inv * gv[v] + bv[v];
                acc[k][j] += wf * y;
            }
        }
    }

    // store out [BT, 64]
    #pragma unroll
    for (int k = 0; k < 4; k++) {
        float4 r = make_float4(acc[k][0], acc[k][1], acc[k][2], acc[k][3]);
        *(float4*)(out + (blk + tokb + k) * (size_t)NU + v0) = r;
    }
}

// ============================================================================
extern "C" void kernel_launch(void* const* d_in, const int* in_sizes, int n_in,
                              void* d_out, int out_size) {
    const float* x    = (const float*)d_in[0];
    const float* W1   = (const float*)d_in[1];
    const float* b1   = (const float*)d_in[2];
    const float* W2   = (const float*)d_in[3];
    const float* b2   = (const float*)d_in[4];
    const float* Wg1  = (const float*)d_in[5];
    const float* bg1  = (const float*)d_in[6];
    const float* Wg2  = (const float*)d_in[7];
    const float* bg2  = (const float*)d_in[8];
    const float* Wp   = (const float*)d_in[9];
    const float* bp   = (const float*)d_in[10];
    const float* gamma= (const float*)d_in[11];
    const float* beta = (const float*)d_in[12];
    const float* w1w  = (const float*)d_in[13];
    const float* b1w  = (const float*)d_in[14];
    const float* w2w  = (const float*)d_in[15];
    const float* b2w  = (const float*)d_in[16];
    const float* wg1w = (const float*)d_in[17];
    const float* bg1w = (const float*)d_in[18];
    const float* wg2w = (const float*)d_in[19];
    const float* bg2w = (const float*)d_in[20];
    const float* gammaw = (const float*)d_in[21];
    const float* betaw  = (const float*)d_in[22];

    float* outp = (float*)d_out;
    float* wp   = outp + W_OFF;   // softmax weights output region

    // K1: weights GRN + softmax
    k_weights<<<BT / 128, 128>>>(x, w1w, b1w, w2w, b2w, wg1w, bg1w, wg2w, bg2w,
                                 gammaw, betaw, wp);

    // K2: per-feature GRNs + weighted sum
    static const int smem_bytes = SM_FLOATS * sizeof(float);
    cudaFuncSetAttribute(k_vsn, cudaFuncAttributeMaxDynamicSharedMemorySize, smem_bytes);
    k_vsn<<<BT / K2_TOK, K2_THREADS, smem_bytes>>>(
        x, W1, b1, W2, b2, Wg1, bg1, Wg2, bg2, Wp, bp, gamma, beta, wp, outp);
}

// round 4
// speedup vs baseline: 3.4901x; 3.4901x over previous
#include <cuda_runtime.h>
#include <cstdint>

#define BT 32768
#define NF 32
#define NU 64
#define EPS 1e-3f
#define W_OFF (BT * NU)

// per-feature image (floats): W2' [64][68] | Wg' [128][68] | vec[8][64]
#define IMG_FLOATS 13568
#define IMG_BYTES  54272
#define OFF_WG     4352          // float offset of Wg'
#define OFF_VEC    13056         // float offset of vec
// smem byte offsets (k_vsn)
#define H2_OFF     54272u        // 4 warps x 32x68 floats = 34816 B
#define XS_OFF     89088u        // 128x33 floats = 16896 B
#define MBAR_OFF   105984u
#define SMEM_TOTAL 106000u

__device__ __align__(16) float g_img[NF][IMG_FLOATS];

// ---------------- helpers ----------------
__device__ __forceinline__ uint32_t smem_u32(const void* p) {
    uint32_t a;
    asm("{ .reg .u64 t; cvta.to.shared.u64 t, %1; cvt.u32.u64 %0, t; }" : "=r"(a) : "l"(p));
    return a;
}
__device__ __forceinline__ uint32_t rna_tf32(float x) {
    uint32_t o;
    asm("cvt.rna.tf32.f32 %0, %1;" : "=r"(o) : "f"(x));
    return o;
}
__device__ __forceinline__ float eluf(float z)  { return z > 0.f ? z : (__expf(z) - 1.f); }
__device__ __forceinline__ float sigmf(float z) { return __fdividef(1.f, 1.f + __expf(-z)); }

__device__ __forceinline__ void mma8(float* c, const uint32_t* a, const uint32_t* b) {
    asm volatile(
        "mma.sync.aligned.m16n8k8.row.col.f32.tf32.tf32.f32 "
        "{%0,%1,%2,%3}, {%4,%5,%6,%7}, {%8,%9}, {%0,%1,%2,%3};"
        : "+f"(c[0]), "+f"(c[1]), "+f"(c[2]), "+f"(c[3])
        : "r"(a[0]), "r"(a[1]), "r"(a[2]), "r"(a[3]), "r"(b[0]), "r"(b[1]));
}

#define MBARRIER_INIT(addr, cnt) \
    asm volatile("mbarrier.init.shared.b64 [%0], %1;" :: "r"(addr), "r"(cnt) : "memory")
#define MBARRIER_EXPECT_TX(addr, tx) \
    asm volatile("mbarrier.arrive.expect_tx.shared.b64 _, [%0], %1;" :: "r"(addr), "r"(tx) : "memory")
#define MBARRIER_WAIT_PARITY(addr, par) do { \
    uint32_t _m = (addr); uint32_t _p = (par); uint32_t _d; \
    asm volatile("{ .reg .pred p; mbarrier.try_wait.parity.acquire.cta.shared::cta.b64 p, [%1], %2; selp.b32 %0, 1, 0, p; }" \
        : "=r"(_d) : "r"(_m), "r"(_p) : "memory"); \
    if (!_d) { \
        asm volatile("{ .reg .pred P1; WL_%=: mbarrier.try_wait.parity.acquire.cta.shared::cta.b64 P1, [%0], %1, 0x989680; @P1 bra.uni WD_%=; bra.uni WL_%=; WD_%=: }" \
            :: "r"(_m), "r"(_p) : "memory"); \
    } } while (0)

__device__ __forceinline__ void bulk_g2s(uint32_t dst, const void* src, uint32_t bytes, uint32_t mbar) {
    asm volatile("cp.async.bulk.shared::cluster.global.mbarrier::complete_tx::bytes [%0], [%1], %2, [%3];"
                 :: "r"(dst), "l"(src), "r"(bytes), "r"(mbar) : "memory");
}

// ============================================================================
// Kernel 0: weights GRN over F=32 + LN + softmax -> w [BT, 32]
// ============================================================================
__global__ __launch_bounds__(128) void k_weights(
    const float* __restrict__ x,
    const float* __restrict__ w1w, const float* __restrict__ b1w,
    const float* __restrict__ w2w, const float* __restrict__ b2w,
    const float* __restrict__ wg1w, const float* __restrict__ bg1w,
    const float* __restrict__ wg2w, const float* __restrict__ bg2w,
    const float* __restrict__ gammaw, const float* __restrict__ betaw,
    float* __restrict__ wout)
{
    __shared__ float s1[1024], s2[1024], sg1[1024], sg2[1024];
    __shared__ float vb1[32], vb2[32], vbg1[32], vbg2[32], vg[32], vbt[32];
    __shared__ float xsh[128 * 33];

    const int tid = threadIdx.x;
    for (int i = tid; i < 1024; i += 128) {
        s1[i] = w1w[i]; s2[i] = w2w[i]; sg1[i] = wg1w[i]; sg2[i] = wg2w[i];
    }
    if (tid < 32) {
        vb1[tid] = b1w[tid];  vb2[tid] = b2w[tid];
        vbg1[tid] = bg1w[tid]; vbg2[tid] = bg2w[tid];
        vg[tid] = gammaw[tid]; vbt[tid] = betaw[tid];
    }
    const int token = blockIdx.x * 128 + tid;
    {
        const float4* xp = (const float4*)(x + (size_t)token * NF);
        #pragma unroll
        for (int i = 0; i < 8; i++) {
            float4 v = xp[i];
            xsh[tid * 33 + i * 4 + 0] = v.x; xsh[tid * 33 + i * 4 + 1] = v.y;
            xsh[tid * 33 + i * 4 + 2] = v.z; xsh[tid * 33 + i * 4 + 3] = v.w;
        }
    }
    __syncthreads();

    float h[32];
    #pragma unroll
    for (int g = 0; g < 32; g++) h[g] = vb1[g];
    for (int f = 0; f < 32; f++) {
        float xv = xsh[tid * 33 + f];
        #pragma unroll
        for (int g = 0; g < 32; g++) h[g] += xv * s1[f * 32 + g];
    }
    #pragma unroll
    for (int g = 0; g < 32; g++) h[g] = (h[g] > 0.f) ? h[g] : (expf(h[g]) - 1.f);

    float h2[32];
    #pragma unroll
    for (int g = 0; g < 32; g++) h2[g] = vb2[g];
    for (int f = 0; f < 32; f++) {
        float hv = h[f];
        #pragma unroll
        for (int g = 0; g < 32; g++) h2[g] += hv * s2[f * 32 + g];
    }

    float o2[32];
    #pragma unroll
    for (int g = 0; g < 32; g++) o2[g] = vbg2[g];
    for (int f = 0; f < 32; f++) {
        float hv = h2[f];
        #pragma unroll
        for (int g = 0; g < 32; g++) o2[g] += hv * sg2[f * 32 + g];
    }
    #pragma unroll
    for (int g = 0; g < 32; g++) o2[g] = 1.f / (1.f + expf(-o2[g]));

    #pragma unroll
    for (int g = 0; g < 32; g++) h[g] = vbg1[g];
    for (int f = 0; f < 32; f++) {
        float hv = h2[f];
        #pragma unroll
        for (int g = 0; g < 32; g++) h[g] += hv * sg1[f * 32 + g];
    }
    #pragma unroll
    for (int g = 0; g < 32; g++) h[g] = h[g] * o2[g] + xsh[tid * 33 + g];

    float sum = 0.f, sq = 0.f;
    #pragma unroll
    for (int g = 0; g < 32; g++) { sum += h[g]; sq += h[g] * h[g]; }
    float mean = sum * (1.f / 32.f);
    float var  = sq * (1.f / 32.f) - mean * mean;
    float inv  = rsqrtf(var + EPS);

    float mx = -1e30f;
    #pragma unroll
    for (int g = 0; g < 32; g++) {
        float y = (h[g] - mean) * inv * vg[g] + vbt[g];
        h[g] = y; mx = fmaxf(mx, y);
    }
    float se = 0.f;
    #pragma unroll
    for (int g = 0; g < 32; g++) { float e = expf(h[g] - mx); h[g] = e; se += e; }
    float r = 1.f / se;
    #pragma unroll
    for (int g = 0; g < 32; g++) wout[(size_t)token * NF + g] = h[g] * r;
}

// ============================================================================
// Kernel 1: prep — per-feature images:
//   W2'[n][u] = tf32(W2[u][n])                  (B of GEMM1, col-major K x N, ld 68)
//   Wg'[n][u] : n<64 -> tf32(Wg1[u][n]); n>=64 -> tf32(Wg2[u][n-64])
//   vec[8][64]: W1,b1,Wp,bp,gamma,beta,be1,be2  (be = bg + b2 @ Wg)
// ============================================================================
__global__ __launch_bounds__(256) void k_prep(
    const float* __restrict__ W2, const float* __restrict__ Wg1, const float* __restrict__ Wg2,
    const float* __restrict__ b2, const float* __restrict__ bg1, const float* __restrict__ bg2,
    const float* __restrict__ W1, const float* __restrict__ b1,
    const float* __restrict__ Wp, const float* __restrict__ bp,
    const float* __restrict__ gamma, const float* __restrict__ beta)
{
    const int f = blockIdx.x;
    const int tid = threadIdx.x;
    const float* W2f  = W2  + (size_t)f * 4096;
    const float* Wg1f = Wg1 + (size_t)f * 4096;
    const float* Wg2f = Wg2 + (size_t)f * 4096;
    float* img = g_img[f];

    for (int i = tid; i < 4096; i += 256) {
        int n = i >> 6, u = i & 63;
        img[n * 68 + u] = __uint_as_float(rna_tf32(W2f[u * 64 + n]));
    }
    for (int i = tid; i < 8192; i += 256) {
        int n = i >> 6, u = i & 63;
        float v = (n < 64) ? Wg1f[u * 64 + n] : Wg2f[u * 64 + (n - 64)];
        img[OFF_WG + n * 68 + u] = __uint_as_float(rna_tf32(v));
    }
    if (tid < 64) {
        int o = f * 64 + tid;
        img[OFF_VEC +   0 + tid] = W1[o];
        img[OFF_VEC +  64 + tid] = b1[o];
        img[OFF_VEC + 128 + tid] = Wp[o];
        img[OFF_VEC + 192 + tid] = bp[o];
        img[OFF_VEC + 256 + tid] = gamma[o];
        img[OFF_VEC + 320 + tid] = beta[o];
        float s1 = bg1[o], s2 = bg2[o];
        for (int u = 0; u < 64; u++) {
            float bv = b2[f * 64 + u];
            s1 += bv * Wg1f[u * 64 + tid];
            s2 += bv * Wg2f[u * 64 + tid];
        }
        img[OFF_VEC + 384 + tid] = s1;
        img[OFF_VEC + 448 + tid] = s2;
    }
}

// ============================================================================
// Kernel 2: main — per-feature GRNs via mma.sync tf32, fused LN + weighted sum.
// CTA = 128 tokens, 4 warps x 32 tokens (two 16-row m-tiles per warp).
// ============================================================================
__global__ __launch_bounds__(128, 2) void k_vsn(
    const float* __restrict__ x,
    const float* __restrict__ w,
    float* __restrict__ out)
{
    extern __shared__ char smem[];
    const uint32_t sbase = smem_u32(smem);
    float* xs = (float*)(smem + XS_OFF);

    const int tid  = threadIdx.x;
    const int lane = tid & 31;
    const int warp = tid >> 5;
    const int q    = lane & 3;       // threadID_in_group
    const int g    = lane >> 2;      // groupID
    const int wtok = warp * 32;
    const size_t blk = (size_t)blockIdx.x * 128;

    float*    h2w = (float*)(smem + H2_OFF) + warp * 2176;     // [32][68]
    uint32_t* h2u = (uint32_t*)h2w;

    const uint32_t mbar = sbase + MBAR_OFF;
    if (tid == 0) MBARRIER_INIT(mbar, 1);

    // stage x tile [128][33]
    {
        const float4* xp = (const float4*)(x + (blk + tid) * NF);
        #pragma unroll
        for (int i = 0; i < 8; i++) {
            float4 v = xp[i];
            xs[tid * 33 + i * 4 + 0] = v.x; xs[tid * 33 + i * 4 + 1] = v.y;
            xs[tid * 33 + i * 4 + 2] = v.z; xs[tid * 33 + i * 4 + 3] = v.w;
        }
    }
    __syncthreads();
    if (tid == 0) {
        MBARRIER_EXPECT_TX(mbar, IMG_BYTES);
        bulk_g2s(sbase, &g_img[0][0], IMG_BYTES, mbar);
    }

    const uint32_t* W2p = (const uint32_t*)smem;               // [64][68]
    const uint32_t* Wgp = (const uint32_t*)smem + OFF_WG;      // [128][68]
    const float*    vecf = (const float*)smem + OFF_VEC;       // [8][64]

    float acc[4][16];
    #pragma unroll
    for (int t = 0; t < 4; t++)
        #pragma unroll
        for (int c = 0; c < 16; c++) acc[t][c] = 0.f;

    #pragma unroll 1
    for (int f = 0; f < NF; f++) {
        MBARRIER_WAIT_PARITY(mbar, f & 1);

        float xf[4], wf[4];
        #pragma unroll
        for (int t = 0; t < 4; t++) {
            int row = g + 8 * t;
            xf[t] = xs[(wtok + row) * 33 + f];
            wf[t] = w[(blk + wtok + row) * NF + f];
        }

        // ---- A1 = tf32(elu(xf*W1+b1)) fragments in registers ----
        uint32_t a1[2][8][4];
        #pragma unroll
        for (int s = 0; s < 8; s++) {
            int u0 = 8 * s + q, u1 = u0 + 4;
            float w1a = vecf[u0], b1a = vecf[64 + u0];
            float w1b = vecf[u1], b1b = vecf[64 + u1];
            #pragma unroll
            for (int m = 0; m < 2; m++) {
                a1[m][s][0] = rna_tf32(eluf(fmaf(xf[2*m],     w1a, b1a)));
                a1[m][s][1] = rna_tf32(eluf(fmaf(xf[2*m + 1], w1a, b1a)));
                a1[m][s][2] = rna_tf32(eluf(fmaf(xf[2*m],     w1b, b1b)));
                a1[m][s][3] = rna_tf32(eluf(fmaf(xf[2*m + 1], w1b, b1b)));
            }
        }

        // ---- GEMM1: h2' = h1 @ W2 -> per-warp smem tile (tf32 bits) ----
        #pragma unroll 2
        for (int j = 0; j < 8; j++) {
            const uint32_t* Brow = W2p + (8 * j + g) * 68 + q;
            float c0[4] = {0.f, 0.f, 0.f, 0.f};
            float c1[4] = {0.f, 0.f, 0.f, 0.f};
            #pragma unroll
            for (int s = 0; s < 8; s++) {
                uint32_t bb[2] = { Brow[8 * s], Brow[8 * s + 4] };
                mma8(c0, a1[0][s], bb);
                mma8(c1, a1[1][s], bb);
            }
            int col0 = 8 * j + 2 * q;
            *(uint2*)&h2u[(g     ) * 68 + col0] = make_uint2(rna_tf32(c0[0]), rna_tf32(c0[1]));
            *(uint2*)&h2u[(g +  8) * 68 + col0] = make_uint2(rna_tf32(c0[2]), rna_tf32(c0[3]));
            *(uint2*)&h2u[(g + 16) * 68 + col0] = make_uint2(rna_tf32(c1[0]), rna_tf32(c1[1]));
            *(uint2*)&h2u[(g + 24) * 68 + col0] = make_uint2(rna_tf32(c1[2]), rna_tf32(c1[3]));
        }
        __syncwarp();

        // ---- A2 fragments from h2 tile ----
        uint32_t a2[2][8][4];
        #pragma unroll
        for (int s = 0; s < 8; s++) {
            int k0 = 8 * s + q, k1 = k0 + 4;
            a2[0][s][0] = h2u[(g     ) * 68 + k0];
            a2[0][s][1] = h2u[(g +  8) * 68 + k0];
            a2[0][s][2] = h2u[(g     ) * 68 + k1];
            a2[0][s][3] = h2u[(g +  8) * 68 + k1];
            a2[1][s][0] = h2u[(g + 16) * 68 + k0];
            a2[1][s][1] = h2u[(g + 24) * 68 + k0];
            a2[1][s][2] = h2u[(g + 16) * 68 + k1];
            a2[1][s][3] = h2u[(g + 24) * 68 + k1];
        }
        __syncwarp();   // tile free -> reused as sv spill

        // ---- GEMM2 (o1 | o2) + gate + residual, pass 1 ----
        float ssum[4] = {0.f, 0.f, 0.f, 0.f};
        float ssq[4]  = {0.f, 0.f, 0.f, 0.f};
        #pragma unroll 1
        for (int j = 0; j < 8; j++) {
            const uint32_t* B1row = Wgp + (8 * j + g) * 68 + q;
            const uint32_t* B2row = Wgp + (64 + 8 * j + g) * 68 + q;
            float c1[8] = {0.f,0.f,0.f,0.f,0.f,0.f,0.f,0.f};
            float c2[8] = {0.f,0.f,0.f,0.f,0.f,0.f,0.f,0.f};
            #pragma unroll
            for (int s = 0; s < 8; s++) {
                uint32_t bb1[2] = { B1row[8 * s], B1row[8 * s + 4] };
                uint32_t bb2[2] = { B2row[8 * s], B2row[8 * s + 4] };
                mma8(c1,     a2[0][s], bb1);
                mma8(c1 + 4, a2[1][s], bb1);
                mma8(c2,     a2[0][s], bb2);
                mma8(c2 + 4, a2[1][s], bb2);
            }
            int col0 = 8 * j + 2 * q;
            float2 be1v = *(const float2*)&vecf[384 + col0];
            float2 be2v = *(const float2*)&vecf[448 + col0];
            float2 wpv  = *(const float2*)&vecf[128 + col0];
            float2 bpv  = *(const float2*)&vecf[192 + col0];
            #pragma unroll
            for (int t = 0; t < 4; t++) {
                int m = t >> 1, r = t & 1;
                float o1a = c1[m * 4 + 2 * r]     + be1v.x;
                float o1b = c1[m * 4 + 2 * r + 1] + be1v.y;
                float o2a = c2[m * 4 + 2 * r]     + be2v.x;
                float o2b = c2[m * 4 + 2 * r + 1] + be2v.y;
                float sv0 = fmaf(o1a, sigmf(o2a), fmaf(xf[t], wpv.x, bpv.x));
                float sv1 = fmaf(o1b, sigmf(o2b), fmaf(xf[t], wpv.y, bpv.y));
                *(float2*)&h2w[(g + 8 * t) * 68 + col0] = make_float2(sv0, sv1);
                ssum[t] += sv0 + sv1;
                ssq[t]  = fmaf(sv0, sv0, fmaf(sv1, sv1, ssq[t]));
            }
        }

        // ---- per-row LN stats (reduce over quad: lanes sharing g) ----
        #pragma unroll
        for (int off = 1; off < 4; off <<= 1) {
            #pragma unroll
            for (int t = 0; t < 4; t++) {
                ssum[t] += __shfl_xor_sync(0xffffffffu, ssum[t], off);
                ssq[t]  += __shfl_xor_sync(0xffffffffu, ssq[t],  off);
            }
        }
        float mean[4], inv[4];
        #pragma unroll
        for (int t = 0; t < 4; t++) {
            mean[t] = ssum[t] * (1.f / 64.f);
            float var = ssq[t] * (1.f / 64.f) - mean[t] * mean[t];
            inv[t] = rsqrtf(var + EPS);
        }

        // ---- pass 2: y = (sv-mean)*inv*gamma+beta ; acc += wf*y ----
        #pragma unroll
        for (int j = 0; j < 8; j++) {
            int col0 = 8 * j + 2 * q;
            float2 gv = *(const float2*)&vecf[256 + col0];
            float2 bv = *(const float2*)&vecf[320 + col0];
            #pragma unroll
            for (int t = 0; t < 4; t++) {
                float2 sv = *(const float2*)&h2w[(g + 8 * t) * 68 + col0];
                float y0 = fmaf((sv.x - mean[t]) * inv[t], gv.x, bv.x);
                float y1 = fmaf((sv.y - mean[t]) * inv[t], gv.y, bv.y);
                acc[t][2 * j]     = fmaf(wf[t], y0, acc[t][2 * j]);
                acc[t][2 * j + 1] = fmaf(wf[t], y1, acc[t][2 * j + 1]);
            }
        }

        __syncthreads();   // all warps done with img buffer + sv tiles
        if (tid == 0 && f + 1 < NF) {
            MBARRIER_EXPECT_TX(mbar, IMG_BYTES);
            bulk_g2s(sbase, &g_img[f + 1][0], IMG_BYTES, mbar);
        }
    }

    // ---- store out [BT, 64] ----
    #pragma unroll
    for (int t = 0; t < 4; t++) {
        float* orow = out + (blk + wtok + g + 8 * t) * (size_t)NU;
        #pragma unroll
        for (int j = 0; j < 8; j++)
            *(float2*)&orow[8 * j + 2 * q] = make_float2(acc[t][2 * j], acc[t][2 * j + 1]);
    }
}

// ============================================================================
extern "C" void kernel_launch(void* const* d_in, const int* in_sizes, int n_in,
                              void* d_out, int out_size) {
    const float* x    = (const float*)d_in[0];
    const float* W1   = (const float*)d_in[1];
    const float* b1   = (const float*)d_in[2];
    const float* W2   = (const float*)d_in[3];
    const float* b2   = (const float*)d_in[4];
    const float* Wg1  = (const float*)d_in[5];
    const float* bg1  = (const float*)d_in[6];
    const float* Wg2  = (const float*)d_in[7];
    const float* bg2  = (const float*)d_in[8];
    const float* Wp   = (const float*)d_in[9];
    const float* bp   = (const float*)d_in[10];
    const float* gamma= (const float*)d_in[11];
    const float* beta = (const float*)d_in[12];
    const float* w1w  = (const float*)d_in[13];
    const float* b1w  = (const float*)d_in[14];
    const float* w2w  = (const float*)d_in[15];
    const float* b2w  = (const float*)d_in[16];
    const float* wg1w = (const float*)d_in[17];
    const float* bg1w = (const float*)d_in[18];
    const float* wg2w = (const float*)d_in[19];
    const float* bg2w = (const float*)d_in[20];
    const float* gammaw = (const float*)d_in[21];
    const float* betaw  = (const float*)d_in[22];

    float* outp = (float*)d_out;
    float* wp   = outp + W_OFF;

    k_weights<<<BT / 128, 128>>>(x, w1w, b1w, w2w, b2w, wg1w, bg1w, wg2w, bg2w,
                                 gammaw, betaw, wp);
    k_prep<<<NF, 256>>>(W2, Wg1, Wg2, b2, bg1, bg2, W1, b1, Wp, bp, gamma, beta);

    cudaFuncSetAttribute(k_vsn, cudaFuncAttributeMaxDynamicSharedMemorySize, SMEM_TOTAL);
    k_vsn<<<BT / 128, 128, SMEM_TOTAL>>>(x, wp, outp);
}

// round 5
// speedup vs baseline: 4.9673x; 1.4232x over previous
#include <cuda_runtime.h>
#include <cuda_fp16.h>
#include <cstdint>

#define BT 32768
#define NF 32
#define NU 64
#define EPS 1e-3f
#define W_OFF (BT * NU)

// per-feature image (bytes): W2' fp16[64][72] | Wg' fp16[128][72] | vec f32[8][64]
#define IMG_BYTES  29696
#define OFF_WG_B   9216
#define OFF_VEC_B  27648
// k_vsn smem byte offsets
#define H2SV_OFF   59392u          // 2 img buffers before this
#define XS_OFF     94208u          // 128*33 floats
#define MBAR_OFF   111104u
#define SMEM_TOTAL 111120u

__device__ __align__(16) unsigned char g_img[NF][IMG_BYTES];

// ---------------- helpers ----------------
__device__ __forceinline__ uint32_t smem_u32(const void* p) {
    uint32_t a;
    asm("{ .reg .u64 t; cvta.to.shared.u64 t, %1; cvt.u32.u64 %0, t; }" : "=r"(a) : "l"(p));
    return a;
}
__device__ __forceinline__ float eluf(float z)  { return z > 0.f ? z : (__expf(z) - 1.f); }
// sigmoid via tanh.approx (1 MUFU):  sig(z) = 0.5*tanh(z/2) + 0.5
__device__ __forceinline__ float sigmf(float z) {
    float t, h = 0.5f * z;
    asm("tanh.approx.f32 %0, %1;" : "=f"(t) : "f"(h));
    return fmaf(0.5f, t, 0.5f);
}
__device__ __forceinline__ uint32_t packh2(float lo, float hi) {
    __half2 h = __floats2half2_rn(lo, hi);
    return *reinterpret_cast<uint32_t*>(&h);
}
__device__ __forceinline__ void mma16(float* c, const uint32_t* a, uint32_t b0, uint32_t b1) {
    asm volatile(
        "mma.sync.aligned.m16n8k16.row.col.f32.f16.f16.f32 "
        "{%0,%1,%2,%3}, {%4,%5,%6,%7}, {%8,%9}, {%0,%1,%2,%3};"
        : "+f"(c[0]), "+f"(c[1]), "+f"(c[2]), "+f"(c[3])
        : "r"(a[0]), "r"(a[1]), "r"(a[2]), "r"(a[3]), "r"(b0), "r"(b1));
}

#define MBARRIER_INIT(addr, cnt) \
    asm volatile("mbarrier.init.shared.b64 [%0], %1;" :: "r"(addr), "r"(cnt) : "memory")
#define MBARRIER_EXPECT_TX(addr, tx) \
    asm volatile("mbarrier.arrive.expect_tx.shared.b64 _, [%0], %1;" :: "r"(addr), "r"(tx) : "memory")
#define MBARRIER_WAIT_PARITY(addr, par) do { \
    uint32_t _m = (addr); uint32_t _p = (par); uint32_t _d; \
    asm volatile("{ .reg .pred p; mbarrier.try_wait.parity.acquire.cta.shared::cta.b64 p, [%1], %2; selp.b32 %0, 1, 0, p; }" \
        : "=r"(_d) : "r"(_m), "r"(_p) : "memory"); \
    if (!_d) { \
        asm volatile("{ .reg .pred P1; WL_%=: mbarrier.try_wait.parity.acquire.cta.shared::cta.b64 P1, [%0], %1, 0x989680; @P1 bra.uni WD_%=; bra.uni WL_%=; WD_%=: }" \
            :: "r"(_m), "r"(_p) : "memory"); \
    } } while (0)

__device__ __forceinline__ void bulk_g2s(uint32_t dst, const void* src, uint32_t bytes, uint32_t mbar) {
    asm volatile("cp.async.bulk.shared::cluster.global.mbarrier::complete_tx::bytes [%0], [%1], %2, [%3];"
                 :: "r"(dst), "l"(src), "r"(bytes), "r"(mbar) : "memory");
}

// ============================================================================
// Kernel 0: weights GRN + LN + softmax -> w [BT,32]
// Block 256 = 128 tokens, 2 threads/token (each owns 16 of 32 outputs).
// ============================================================================
#define KW_S1 0
#define KW_S2 1024
#define KW_G1 2048
#define KW_G2 3072
#define KW_VB 4096        // 6*32
#define KW_X  4288        // 128*36
#define KW_H  8896
#define KW_H2 13504
#define KW_FLOATS 18112   // 72448 bytes

__global__ __launch_bounds__(256) void k_weights(
    const float* __restrict__ x,
    const float* __restrict__ w1w, const float* __restrict__ b1w,
    const float* __restrict__ w2w, const float* __restrict__ b2w,
    const float* __restrict__ wg1w, const float* __restrict__ bg1w,
    const float* __restrict__ wg2w, const float* __restrict__ bg2w,
    const float* __restrict__ gammaw, const float* __restrict__ betaw,
    float* __restrict__ wout)
{
    extern __shared__ float sw[];
    const int tid = threadIdx.x;
    for (int i = tid; i < 1024; i += 256) {
        sw[KW_S1 + i] = w1w[i]; sw[KW_S2 + i] = w2w[i];
        sw[KW_G1 + i] = wg1w[i]; sw[KW_G2 + i] = wg2w[i];
    }
    if (tid < 32) {
        sw[KW_VB + tid]       = b1w[tid];
        sw[KW_VB + 32 + tid]  = b2w[tid];
        sw[KW_VB + 64 + tid]  = bg1w[tid];
        sw[KW_VB + 96 + tid]  = bg2w[tid];
        sw[KW_VB + 128 + tid] = gammaw[tid];
        sw[KW_VB + 160 + tid] = betaw[tid];
    }
    const int tok  = tid >> 1;
    const int gb   = (tid & 1) * 16;
    const size_t tokG = (size_t)blockIdx.x * 128 + tok;
    {
        const float4* xp = (const float4*)(x + tokG * 32 + gb);
        float4* xr = (float4*)&sw[KW_X + tok * 36 + gb];
        #pragma unroll
        for (int c = 0; c < 4; c++) xr[c] = xp[c];
    }
    __syncthreads();

    float h[16];
    #pragma unroll
    for (int g = 0; g < 16; g++) h[g] = sw[KW_VB + gb + g];
    for (int f = 0; f < 32; f++) {
        float xv = sw[KW_X + tok * 36 + f];
        const float4* wr = (const float4*)&sw[KW_S1 + f * 32 + gb];
        #pragma unroll
        for (int c = 0; c < 4; c++) {
            float4 wv = wr[c];
            h[4*c+0] += xv * wv.x; h[4*c+1] += xv * wv.y;
            h[4*c+2] += xv * wv.z; h[4*c+3] += xv * wv.w;
        }
    }
    #pragma unroll
    for (int g = 0; g < 16; g++) {
        float v = h[g];
        sw[KW_H + tok * 36 + gb + g] = (v > 0.f) ? v : (__expf(v) - 1.f);
    }
    __syncthreads();

    float h2[16];
    #pragma unroll
    for (int g = 0; g < 16; g++) h2[g] = sw[KW_VB + 32 + gb + g];
    for (int f = 0; f < 32; f++) {
        float hv = sw[KW_H + tok * 36 + f];
        const float4* wr = (const float4*)&sw[KW_S2 + f * 32 + gb];
        #pragma unroll
        for (int c = 0; c < 4; c++) {
            float4 wv = wr[c];
            h2[4*c+0] += hv * wv.x; h2[4*c+1] += hv * wv.y;
            h2[4*c+2] += hv * wv.z; h2[4*c+3] += hv * wv.w;
        }
    }
    #pragma unroll
    for (int g = 0; g < 16; g++) sw[KW_H2 + tok * 36 + gb + g] = h2[g];
    __syncthreads();

    float o1[16], o2[16];
    #pragma unroll
    for (int g = 0; g < 16; g++) { o1[g] = sw[KW_VB + 64 + gb + g]; o2[g] = sw[KW_VB + 96 + gb + g]; }
    for (int f = 0; f < 32; f++) {
        float hv = sw[KW_H2 + tok * 36 + f];
        const float4* w1r = (const float4*)&sw[KW_G1 + f * 32 + gb];
        const float4* w2r = (const float4*)&sw[KW_G2 + f * 32 + gb];
        #pragma unroll
        for (int c = 0; c < 4; c++) {
            float4 wa = w1r[c], wb = w2r[c];
            o1[4*c+0] += hv * wa.x; o1[4*c+1] += hv * wa.y;
            o1[4*c+2] += hv * wa.z; o1[4*c+3] += hv * wa.w;
            o2[4*c+0] += hv * wb.x; o2[4*c+1] += hv * wb.y;
            o2[4*c+2] += hv * wb.z; o2[4*c+3] += hv * wb.w;
        }
    }

    float s[16], ssum = 0.f, ssq = 0.f;
    #pragma unroll
    for (int g = 0; g < 16; g++) {
        float sg = 1.f / (1.f + __expf(-o2[g]));
        float v = o1[g] * sg + sw[KW_X + tok * 36 + gb + g];
        s[g] = v; ssum += v; ssq += v * v;
    }
    ssum += __shfl_xor_sync(0xffffffffu, ssum, 1);
    ssq  += __shfl_xor_sync(0xffffffffu, ssq, 1);
    float mean = ssum * (1.f / 32.f);
    float var  = ssq * (1.f / 32.f) - mean * mean;
    float inv  = rsqrtf(var + EPS);

    float y[16], mx = -1e30f;
    #pragma unroll
    for (int g = 0; g < 16; g++) {
        float v = (s[g] - mean) * inv * sw[KW_VB + 128 + gb + g] + sw[KW_VB + 160 + gb + g];
        y[g] = v; mx = fmaxf(mx, v);
    }
    mx = fmaxf(mx, __shfl_xor_sync(0xffffffffu, mx, 1));
    float se = 0.f;
    #pragma unroll
    for (int g = 0; g < 16; g++) { float e = __expf(y[g] - mx); y[g] = e; se += e; }
    se += __shfl_xor_sync(0xffffffffu, se, 1);
    float r = 1.f / se;
    {
        float4* op = (float4*)(wout + tokG * 32 + gb);
        #pragma unroll
        for (int c = 0; c < 4; c++)
            op[c] = make_float4(y[4*c] * r, y[4*c+1] * r, y[4*c+2] * r, y[4*c+3] * r);
    }
}

// ============================================================================
// Kernel 1: prep — per-feature fp16 images + folded gate biases.
//   W2'[n][k] = fp16(W2[k][n])   (ld 72 halves)
//   Wg'[n][k] : n<64 -> Wg1 col n ; n>=64 -> Wg2 col n-64
//   vec f32[8][64]: W1,b1,Wp,bp,gamma,beta,be1,be2  (be = bg + b2 @ Wg)
// ============================================================================
__global__ __launch_bounds__(256) void k_prep(
    const float* __restrict__ W2, const float* __restrict__ Wg1, const float* __restrict__ Wg2,
    const float* __restrict__ b2, const float* __restrict__ bg1, const float* __restrict__ bg2,
    const float* __restrict__ W1, const float* __restrict__ b1,
    const float* __restrict__ Wp, const float* __restrict__ bp,
    const float* __restrict__ gamma, const float* __restrict__ beta)
{
    const int f = blockIdx.x;
    const int tid = threadIdx.x;
    const float* W2f  = W2  + (size_t)f * 4096;
    const float* Wg1f = Wg1 + (size_t)f * 4096;
    const float* Wg2f = Wg2 + (size_t)f * 4096;
    unsigned char* img = g_img[f];
    __half* W2h = (__half*)img;
    __half* Wgh = (__half*)(img + OFF_WG_B);
    float*  vec = (float*)(img + OFF_VEC_B);

    for (int i = tid; i < 4096; i += 256) {
        int n = i >> 6, k = i & 63;
        W2h[n * 72 + k] = __float2half_rn(W2f[k * 64 + n]);
    }
    for (int i = tid; i < 8192; i += 256) {
        int n = i >> 6, k = i & 63;
        float v = (n < 64) ? Wg1f[k * 64 + n] : Wg2f[k * 64 + (n - 64)];
        Wgh[n * 72 + k] = __float2half_rn(v);
    }
    if (tid < 64) {
        int o = f * 64 + tid;
        vec[0   + tid] = W1[o];
        vec[64  + tid] = b1[o];
        vec[128 + tid] = Wp[o];
        vec[192 + tid] = bp[o];
        vec[256 + tid] = gamma[o];
        vec[320 + tid] = beta[o];
        float s1 = bg1[o], s2 = bg2[o];
        for (int u = 0; u < 64; u++) {
            float bv = b2[f * 64 + u];
            s1 += bv * Wg1f[u * 64 + tid];
            s2 += bv * Wg2f[u * 64 + tid];
        }
        vec[384 + tid] = s1;
        vec[448 + tid] = s2;
    }
}

// ============================================================================
// Kernel 2: main — per-feature GRNs via mma.sync fp16 (m16n8k16), fused LN.
// CTA = 128 tokens, 4 warps x 32 tokens. Double-buffered weight images.
// ============================================================================
__global__ __launch_bounds__(128, 2) void k_vsn(
    const float* __restrict__ x,
    const float* __restrict__ w,
    float* __restrict__ out)
{
    extern __shared__ char smem[];
    const uint32_t sbase = smem_u32(smem);
    float* xs = (float*)(smem + XS_OFF);

    const int tid  = threadIdx.x;
    const int lane = tid & 31;
    const int warp = tid >> 5;
    const int q    = lane & 3;
    const int g    = lane >> 2;
    const int wtok = warp * 32;
    const size_t blk = (size_t)blockIdx.x * 128;

    uint32_t* h2u = (uint32_t*)(smem + H2SV_OFF) + warp * 2176;   // fp16 [32][72] as words
    float*    svw = (float*)(smem + H2SV_OFF) + warp * 2176;      // f32 [32][68] (same region)

    const uint32_t mbar0 = sbase + MBAR_OFF;
    const uint32_t mbar1 = sbase + MBAR_OFF + 8;
    if (tid == 0) { MBARRIER_INIT(mbar0, 1); MBARRIER_INIT(mbar1, 1); }

    {   // stage x tile [128][33]
        const float4* xp = (const float4*)(x + (blk + tid) * NF);
        #pragma unroll
        for (int i = 0; i < 8; i++) {
            float4 v = xp[i];
            xs[tid * 33 + i * 4 + 0] = v.x; xs[tid * 33 + i * 4 + 1] = v.y;
            xs[tid * 33 + i * 4 + 2] = v.z; xs[tid * 33 + i * 4 + 3] = v.w;
        }
    }
    __syncthreads();
    if (tid == 0) {
        MBARRIER_EXPECT_TX(mbar0, IMG_BYTES);
        bulk_g2s(sbase, &g_img[0][0], IMG_BYTES, mbar0);
        MBARRIER_EXPECT_TX(mbar1, IMG_BYTES);
        bulk_g2s(sbase + IMG_BYTES, &g_img[1][0], IMG_BYTES, mbar1);
    }

    float acc[4][16];
    #pragma unroll
    for (int t = 0; t < 4; t++)
        #pragma unroll
        for (int c = 0; c < 16; c++) acc[t][c] = 0.f;

    #pragma unroll 1
    for (int f = 0; f < NF; f++) {
        const int buf = f & 1;
        MBARRIER_WAIT_PARITY(buf ? mbar1 : mbar0, (f >> 1) & 1);

        const uint32_t* bw   = (const uint32_t*)(smem + buf * IMG_BYTES);            // W2'
        const uint32_t* wgw  = (const uint32_t*)(smem + buf * IMG_BYTES + OFF_WG_B); // Wg'
        const float*    vecf = (const float*)(smem + buf * IMG_BYTES + OFF_VEC_B);

        float xf[4], wf[4];
        #pragma unroll
        for (int t = 0; t < 4; t++) {
            int row = g + 8 * t;
            xf[t] = xs[(wtok + row) * 33 + f];
            wf[t] = w[(blk + wtok + row) * NF + f];
        }

        // ---- A1 = fp16(elu(xf*W1+b1)) fragments ----
        uint32_t a1[2][4][4];
        #pragma unroll
        for (int s = 0; s < 4; s++) {
            #pragma unroll
            for (int p = 0; p < 2; p++) {
                int u0 = 16 * s + 2 * q + 8 * p;
                float wa = vecf[u0],     ba = vecf[64 + u0];
                float wb = vecf[u0 + 1], bb = vecf[64 + u0 + 1];
                #pragma unroll
                for (int m = 0; m < 2; m++) {
                    a1[m][s][2*p]   = packh2(eluf(fmaf(xf[2*m],   wa, ba)),
                                             eluf(fmaf(xf[2*m],   wb, bb)));
                    a1[m][s][2*p+1] = packh2(eluf(fmaf(xf[2*m+1], wa, ba)),
                                             eluf(fmaf(xf[2*m+1], wb, bb)));
                }
            }
        }

        // ---- GEMM1: h2' = h1 @ W2  -> fp16 per-warp tile ----
        #pragma unroll 2
        for (int j = 0; j < 8; j++) {
            const uint32_t* Br = bw + (8 * j + g) * 36 + q;
            float c0[4] = {0.f,0.f,0.f,0.f};
            float c1[4] = {0.f,0.f,0.f,0.f};
            #pragma unroll
            for (int s = 0; s < 4; s++) {
                uint32_t b0 = Br[8 * s], b1v = Br[8 * s + 4];
                mma16(c0, a1[0][s], b0, b1v);
                mma16(c1, a1[1][s], b0, b1v);
            }
            int cw = 4 * j + q;
            h2u[(g     ) * 36 + cw] = packh2(c0[0], c0[1]);
            h2u[(g +  8) * 36 + cw] = packh2(c0[2], c0[3]);
            h2u[(g + 16) * 36 + cw] = packh2(c1[0], c1[1]);
            h2u[(g + 24) * 36 + cw] = packh2(c1[2], c1[3]);
        }
        __syncwarp();

        // ---- A2 fragments from fp16 h2 tile ----
        uint32_t a2[2][4][4];
        #pragma unroll
        for (int m = 0; m < 2; m++)
            #pragma unroll
            for (int s = 0; s < 4; s++) {
                int r0 = (16 * m + g) * 36 + 8 * s + q;
                a2[m][s][0] = h2u[r0];
                a2[m][s][1] = h2u[r0 + 288];       // +8 rows
                a2[m][s][2] = h2u[r0 + 4];
                a2[m][s][3] = h2u[r0 + 292];
            }
        __syncwarp();   // tile now reused as f32 sv spill

        // ---- GEMM2 (o1 | o2) + gate + residual ----
        float ssum[4] = {0.f,0.f,0.f,0.f};
        float ssq[4]  = {0.f,0.f,0.f,0.f};
        #pragma unroll 1
        for (int j = 0; j < 8; j++) {
            const uint32_t* B1r = wgw + (8 * j + g) * 36 + q;
            const uint32_t* B2r = B1r + 2304;      // +64 rows
            float c1[8] = {0.f,0.f,0.f,0.f,0.f,0.f,0.f,0.f};
            float c2[8] = {0.f,0.f,0.f,0.f,0.f,0.f,0.f,0.f};
            #pragma unroll
            for (int s = 0; s < 4; s++) {
                uint32_t b10 = B1r[8 * s], b11 = B1r[8 * s + 4];
                uint32_t b20 = B2r[8 * s], b21 = B2r[8 * s + 4];
                mma16(c1,     a2[0][s], b10, b11);
                mma16(c1 + 4, a2[1][s], b10, b11);
                mma16(c2,     a2[0][s], b20, b21);
                mma16(c2 + 4, a2[1][s], b20, b21);
            }
            int col0 = 8 * j + 2 * q;
            float2 be1v = *(const float2*)&vecf[384 + col0];
            float2 be2v = *(const float2*)&vecf[448 + col0];
            float2 wpv  = *(const float2*)&vecf[128 + col0];
            float2 bpv  = *(const float2*)&vecf[192 + col0];
            #pragma unroll
            for (int t = 0; t < 4; t++) {
                int m = t >> 1, r = t & 1;
                float o1a = c1[m * 4 + 2 * r]     + be1v.x;
                float o1b = c1[m * 4 + 2 * r + 1] + be1v.y;
                float o2a = c2[m * 4 + 2 * r]     + be2v.x;
                float o2b = c2[m * 4 + 2 * r + 1] + be2v.y;
                float sv0 = fmaf(o1a, sigmf(o2a), fmaf(xf[t], wpv.x, bpv.x));
                float sv1 = fmaf(o1b, sigmf(o2b), fmaf(xf[t], wpv.y, bpv.y));
                *(float2*)&svw[(g + 8 * t) * 68 + col0] = make_float2(sv0, sv1);
                ssum[t] += sv0 + sv1;
                ssq[t]  = fmaf(sv0, sv0, fmaf(sv1, sv1, ssq[t]));
            }
        }

        // ---- per-row LN stats (quad reduce) ----
        #pragma unroll
        for (int off = 1; off < 4; off <<= 1) {
            #pragma unroll
            for (int t = 0; t < 4; t++) {
                ssum[t] += __shfl_xor_sync(0xffffffffu, ssum[t], off);
                ssq[t]  += __shfl_xor_sync(0xffffffffu, ssq[t],  off);
            }
        }
        float mean[4], inv[4];
        #pragma unroll
        for (int t = 0; t < 4; t++) {
            mean[t] = ssum[t] * (1.f / 64.f);
            float var = ssq[t] * (1.f / 64.f) - mean[t] * mean[t];
            inv[t] = rsqrtf(var + EPS);
        }

        // ---- pass 2: normalize + weighted accumulate ----
        #pragma unroll
        for (int j = 0; j < 8; j++) {
            int col0 = 8 * j + 2 * q;
            float2 gv = *(const float2*)&vecf[256 + col0];
            float2 bv = *(const float2*)&vecf[320 + col0];
            #pragma unroll
            for (int t = 0; t < 4; t++) {
                float2 sv = *(const float2*)&svw[(g + 8 * t) * 68 + col0];
                float y0 = fmaf((sv.x - mean[t]) * inv[t], gv.x, bv.x);
                float y1 = fmaf((sv.y - mean[t]) * inv[t], gv.y, bv.y);
                acc[t][2 * j]     = fmaf(wf[t], y0, acc[t][2 * j]);
                acc[t][2 * j + 1] = fmaf(wf[t], y1, acc[t][2 * j + 1]);
            }
        }

        __syncthreads();   // all warps done with buf before it is refilled
        if (tid == 0 && f + 2 < NF) {
            uint32_t mb = buf ? mbar1 : mbar0;
            MBARRIER_EXPECT_TX(mb, IMG_BYTES);
            bulk_g2s(sbase + buf * IMG_BYTES, &g_img[f + 2][0], IMG_BYTES, mb);
        }
    }

    // ---- store out [BT, 64] ----
    #pragma unroll
    for (int t = 0; t < 4; t++) {
        float* orow = out + (blk + wtok + g + 8 * t) * (size_t)NU;
        #pragma unroll
        for (int j = 0; j < 8; j++)
            *(float2*)&orow[8 * j + 2 * q] = make_float2(acc[t][2 * j], acc[t][2 * j + 1]);
    }
}

// ============================================================================
extern "C" void kernel_launch(void* const* d_in, const int* in_sizes, int n_in,
                              void* d_out, int out_size) {
    const float* x    = (const float*)d_in[0];
    const float* W1   = (const float*)d_in[1];
    const float* b1   = (const float*)d_in[2];
    const float* W2   = (const float*)d_in[3];
    const float* b2   = (const float*)d_in[4];
    const float* Wg1  = (const float*)d_in[5];
    const float* bg1  = (const float*)d_in[6];
    const float* Wg2  = (const float*)d_in[7];
    const float* bg2  = (const float*)d_in[8];
    const float* Wp   = (const float*)d_in[9];
    const float* bp   = (const float*)d_in[10];
    const float* gamma= (const float*)d_in[11];
    const float* beta = (const float*)d_in[12];
    const float* w1w  = (const float*)d_in[13];
    const float* b1w  = (const float*)d_in[14];
    const float* w2w  = (const float*)d_in[15];
    const float* b2w  = (const float*)d_in[16];
    const float* wg1w = (const float*)d_in[17];
    const float* bg1w = (const float*)d_in[18];
    const float* wg2w = (const float*)d_in[19];
    const float* bg2w = (const float*)d_in[20];
    const float* gammaw = (const float*)d_in[21];
    const float* betaw  = (const float*)d_in[22];

    float* outp = (float*)d_out;
    float* wp   = outp + W_OFF;

    cudaFuncSetAttribute(k_weights, cudaFuncAttributeMaxDynamicSharedMemorySize,
                         KW_FLOATS * sizeof(float));
    k_weights<<<BT / 128, 256, KW_FLOATS * sizeof(float)>>>(
        x, w1w, b1w, w2w, b2w, wg1w, bg1w, wg2w, bg2w, gammaw, betaw, wp);

    k_prep<<<NF, 256>>>(W2, Wg1, Wg2, b2, bg1, bg2, W1, b1, Wp, bp, gamma, beta);

    cudaFuncSetAttribute(k_vsn, cudaFuncAttributeMaxDynamicSharedMemorySize, SMEM_TOTAL);
    k_vsn<<<BT / 128, 128, SMEM_TOTAL>>>(x, wp, outp);
}